// round 1
// baseline (speedup 1.0000x reference)
#include <cuda_runtime.h>
#include <math.h>

// QuantumPoolingLayer: pool 64x64 -> 2x2 quadrant means over [64,64,64,512] fp32,
// tanh, then 4-qubit circuit (RY embed, 2x [Rot x4 + 6 CNOTs]), output <Z0>.
// Memory-bound: 512 MiB streamed once. Fused single kernel, no scratch.

#define NQ 4

struct c32 { float x, y; };
__device__ __forceinline__ c32 cadd(c32 a, c32 b){ return {a.x+b.x, a.y+b.y}; }
__device__ __forceinline__ c32 cmul(c32 a, c32 b){
    return { fmaf(a.x, b.x, -a.y*b.y), fmaf(a.x, b.y, a.y*b.x) };
}

// Simulate one sample. x[4] = tanh-normalized pooled values, w -> 24 floats
// laid out [layer][qubit][phi,theta,omega]. Returns <Z0> = P(q0=0) - P(q0=1).
__device__ __forceinline__ float simulate_sample(const float x[4], const float* __restrict__ w)
{
    c32 s[16];
#pragma unroll
    for (int k = 0; k < 16; k++) s[k] = {0.f, 0.f};
    s[0].x = 1.f;

    // Initial RY(x*pi) on each wire. wire q <-> bit (3-q) => mask = 8>>q.
#pragma unroll
    for (int q = 0; q < NQ; q++) {
        float half = x[q] * 1.57079632679489662f;   // (x*pi)/2
        float sn, cs; __sincosf(half, &sn, &cs);
        // use accurate sincosf for safety
        sincosf(half, &sn, &cs);
        const int m = 8 >> q;
#pragma unroll
        for (int k = 0; k < 16; k++) {
            if (!(k & m)) {
                c32 v0 = s[k], v1 = s[k | m];
                s[k]     = { cs*v0.x - sn*v1.x, cs*v0.y - sn*v1.y };
                s[k | m] = { sn*v0.x + cs*v1.x, sn*v0.y + cs*v1.y };
            }
        }
    }

#pragma unroll
    for (int layer = 0; layer < 2; layer++) {
        // Rot(phi,theta,omega) = RZ(om) RY(th) RZ(phi) on each wire
#pragma unroll
        for (int q = 0; q < NQ; q++) {
            const float* g = w + (layer * 4 + q) * 3;
            float phi = g[0], th = g[1], om = g[2];
            float stt, ctt; sincosf(0.5f * th, &stt, &ctt);
            float sa, ca;  sincosf(0.5f * (phi + om), &sa, &ca);
            float sb, cb;  sincosf(0.5f * (phi - om), &sb, &cb);
            c32 U00 = { ctt * ca, -ctt * sa };
            c32 U01 = { -stt * cb, -stt * sb };
            c32 U10 = { stt * cb, -stt * sb };
            c32 U11 = { ctt * ca,  ctt * sa };
            const int m = 8 >> q;
#pragma unroll
            for (int k = 0; k < 16; k++) {
                if (!(k & m)) {
                    c32 v0 = s[k], v1 = s[k | m];
                    s[k]     = cadd(cmul(U00, v0), cmul(U01, v1));
                    s[k | m] = cadd(cmul(U10, v0), cmul(U11, v1));
                }
            }
        }
        // CNOT(c,t) for all pairs c<t, in order. Pure amplitude swaps.
#pragma unroll
        for (int c = 0; c < NQ; c++) {
#pragma unroll
            for (int t = c + 1; t < NQ; t++) {
                const int cm = 8 >> c, tm = 8 >> t;
#pragma unroll
                for (int k = 0; k < 16; k++) {
                    if ((k & cm) && !(k & tm)) {
                        c32 tmp = s[k]; s[k] = s[k | tm]; s[k | tm] = tmp;
                    }
                }
            }
        }
    }

    float p = 0.f;
#pragma unroll
    for (int k = 0; k < 16; k++) {
        float pr = fmaf(s[k].x, s[k].x, s[k].y * s[k].y);
        p += (k < 8) ? pr : -pr;
    }
    return p;
}

// Block: 512 threads. blockIdx = (m_chunk in [0,16), b in [0,64)).
// Each block: all 64 rows x 64 cols x 32 m-values (float4 lanes), 512 KiB read.
// Thread (lane = tid&7 -> 4 consecutive m, g = tid>>3 -> row) accumulates
// two j-half partial sums; smem reduce by quadrant; warp 0 simulates 32 samples.
__global__ void __launch_bounds__(512, 4)
qpl_kernel(const float* __restrict__ in, const float* __restrict__ w, float* __restrict__ out)
{
    const int mc = blockIdx.x;       // m chunk: 32 m-values
    const int b  = blockIdx.y;
    const int tid  = threadIdx.x;
    const int lane = tid & 7;        // float4 lane: m_local = lane*4 .. +3
    const int g    = tid >> 3;       // row 0..63

    const float* base = in
        + (((size_t)b * 64 + g) * 64) * 512   // (b, row, j=0, m=0)
        + mc * 32 + (lane << 2);

    float4 a0 = {0.f,0.f,0.f,0.f};   // j in [0,32)
    float4 a1 = {0.f,0.f,0.f,0.f};   // j in [32,64)
#pragma unroll 8
    for (int j = 0; j < 32; j++) {
        float4 v = *reinterpret_cast<const float4*>(base + (size_t)j * 512);
        a0.x += v.x; a0.y += v.y; a0.z += v.z; a0.w += v.w;
    }
#pragma unroll 8
    for (int j = 32; j < 64; j++) {
        float4 v = *reinterpret_cast<const float4*>(base + (size_t)j * 512);
        a1.x += v.x; a1.y += v.y; a1.z += v.z; a1.w += v.w;
    }

    const int ihi = g >> 5;          // row half
    __shared__ float4 part[4][32][8];            // [quad][row-subgroup][lane], 16 KB
    __shared__ float  quads[4][32];              // [quad][m_local]
    part[ihi * 2 + 0][g & 31][lane] = a0;
    part[ihi * 2 + 1][g & 31][lane] = a1;
    __syncthreads();

    if (tid < 32) {
        // Reduce 32 row-partials per (quad, lane)
        const int quad = tid >> 3, ln = tid & 7;
        float4 ssum = {0.f,0.f,0.f,0.f};
#pragma unroll
        for (int k = 0; k < 32; k++) {
            float4 v = part[quad][k][ln];
            ssum.x += v.x; ssum.y += v.y; ssum.z += v.z; ssum.w += v.w;
        }
        quads[quad][ln * 4 + 0] = ssum.x;
        quads[quad][ln * 4 + 1] = ssum.y;
        quads[quad][ln * 4 + 2] = ssum.z;
        quads[quad][ln * 4 + 3] = ssum.w;
        __syncwarp();

        // Each of the 32 threads simulates one sample
        const int mm = mc * 32 + tid;            // global m in [0,512)
        float x[4];
#pragma unroll
        for (int q = 0; q < 4; q++)
            x[q] = tanhf(quads[q][tid] * (1.0f / 1024.0f));

        // widx = (b*512 + mm) // 64 = b*8 + (mm >> 6); 24 floats per widx
        const float* wp = w + ((size_t)(b * 8 + (mm >> 6))) * 24;
        out[b * 512 + mm] = simulate_sample(x, wp);
    }
}

extern "C" void kernel_launch(void* const* d_in, const int* in_sizes, int n_in,
                              void* d_out, int out_size)
{
    const float* in = (const float*)d_in[0];
    const float* w  = (const float*)d_in[1];
    // Defensive: identify tensors by size (inputs = 134217728 elems, weights = 12288)
    if (n_in >= 2 && in_sizes[0] < in_sizes[1]) {
        in = (const float*)d_in[1];
        w  = (const float*)d_in[0];
    }
    dim3 grid(16, 64);
    qpl_kernel<<<grid, 512>>>(in, w, (float*)d_out);
}

// round 2
// speedup vs baseline: 1.1160x; 1.1160x over previous
#include <cuda_runtime.h>
#include <math.h>

// QuantumPoolingLayer: pool 64x64 -> 2x2 quadrant means over [64,64,64,512] fp32,
// tanh, then 4-qubit circuit (RY embed, 2x [Rot x4 + 6 CNOTs]), output <Z0>.
// Memory-bound: 512 MiB streamed once. R2: 64 regs/thread, batched loads (MLP=8),
// __ldcs streaming loads, fast sincos in the (tiny) sim tail.

#define NQ 4

struct c32 { float x, y; };
__device__ __forceinline__ c32 cadd(c32 a, c32 b){ return {a.x+b.x, a.y+b.y}; }
__device__ __forceinline__ c32 cmul(c32 a, c32 b){
    return { fmaf(a.x, b.x, -a.y*b.y), fmaf(a.x, b.y, a.y*b.x) };
}

// Simulate one sample. x[4] = tanh-normalized pooled values, w -> 24 floats
// [layer][qubit][phi,theta,omega]. Returns <Z0> = P(q0=0) - P(q0=1).
__device__ __forceinline__ float simulate_sample(const float x[4], const float* __restrict__ w)
{
    c32 s[16];
#pragma unroll
    for (int k = 0; k < 16; k++) s[k] = {0.f, 0.f};
    s[0].x = 1.f;

    // Initial RY(x*pi) on each wire. wire q <-> bit (3-q) => mask = 8>>q.
#pragma unroll
    for (int q = 0; q < NQ; q++) {
        float half = x[q] * 1.57079632679489662f;   // (x*pi)/2
        float sn, cs; __sincosf(half, &sn, &cs);
        const int m = 8 >> q;
#pragma unroll
        for (int k = 0; k < 16; k++) {
            if (!(k & m)) {
                c32 v0 = s[k], v1 = s[k | m];
                s[k]     = { cs*v0.x - sn*v1.x, cs*v0.y - sn*v1.y };
                s[k | m] = { sn*v0.x + cs*v1.x, sn*v0.y + cs*v1.y };
            }
        }
    }

#pragma unroll
    for (int layer = 0; layer < 2; layer++) {
        // Rot(phi,theta,omega) = RZ(om) RY(th) RZ(phi) on each wire
#pragma unroll
        for (int q = 0; q < NQ; q++) {
            const float* g = w + (layer * 4 + q) * 3;
            float phi = g[0], th = g[1], om = g[2];
            float stt, ctt; __sincosf(0.5f * th, &stt, &ctt);
            float sa, ca;  __sincosf(0.5f * (phi + om), &sa, &ca);
            float sb, cb;  __sincosf(0.5f * (phi - om), &sb, &cb);
            c32 U00 = { ctt * ca, -ctt * sa };
            c32 U01 = { -stt * cb, -stt * sb };
            c32 U10 = { stt * cb, -stt * sb };
            c32 U11 = { ctt * ca,  ctt * sa };
            const int m = 8 >> q;
#pragma unroll
            for (int k = 0; k < 16; k++) {
                if (!(k & m)) {
                    c32 v0 = s[k], v1 = s[k | m];
                    s[k]     = cadd(cmul(U00, v0), cmul(U01, v1));
                    s[k | m] = cadd(cmul(U10, v0), cmul(U11, v1));
                }
            }
        }
        // CNOT(c,t) for all pairs c<t, in order. Pure amplitude swaps.
#pragma unroll
        for (int c = 0; c < NQ; c++) {
#pragma unroll
            for (int t = c + 1; t < NQ; t++) {
                const int cm = 8 >> c, tm = 8 >> t;
#pragma unroll
                for (int k = 0; k < 16; k++) {
                    if ((k & cm) && !(k & tm)) {
                        c32 tmp = s[k]; s[k] = s[k | tm]; s[k | tm] = tmp;
                    }
                }
            }
        }
    }

    float p = 0.f;
#pragma unroll
    for (int k = 0; k < 16; k++) {
        float pr = fmaf(s[k].x, s[k].x, s[k].y * s[k].y);
        p += (k < 8) ? pr : -pr;
    }
    return p;
}

// Block: 512 threads, 2 blocks/SM (64 regs/thread for deep load batching).
// blockIdx = (m_chunk in [0,16), b in [0,64)). Each block: 64 rows x 64 cols
// x 32 m (float4 lanes) = 512 KiB. Thread (lane=tid&7 -> 4 consecutive m,
// g=tid>>3 -> row) accumulates two j-half partials with 8 loads in flight.
__global__ void __launch_bounds__(512, 2)
qpl_kernel(const float* __restrict__ in, const float* __restrict__ w, float* __restrict__ out)
{
    const int mc = blockIdx.x;       // m chunk: 32 m-values
    const int b  = blockIdx.y;
    const int tid  = threadIdx.x;
    const int lane = tid & 7;        // float4 lane: m_local = lane*4 .. +3
    const int g    = tid >> 3;       // row 0..63

    const float* base = in
        + (((size_t)b * 64 + g) * 64) * 512   // (b, row, j=0, m=0)
        + mc * 32 + (lane << 2);

    float4 a0 = {0.f,0.f,0.f,0.f};   // j in [0,32)
    float4 a1 = {0.f,0.f,0.f,0.f};   // j in [32,64)

#pragma unroll
    for (int j0 = 0; j0 < 32; j0 += 8) {
        float4 v[8];
#pragma unroll
        for (int k = 0; k < 8; k++)
            v[k] = __ldcs(reinterpret_cast<const float4*>(base + (size_t)(j0 + k) * 512));
#pragma unroll
        for (int k = 0; k < 8; k++) {
            a0.x += v[k].x; a0.y += v[k].y; a0.z += v[k].z; a0.w += v[k].w;
        }
    }
#pragma unroll
    for (int j0 = 32; j0 < 64; j0 += 8) {
        float4 v[8];
#pragma unroll
        for (int k = 0; k < 8; k++)
            v[k] = __ldcs(reinterpret_cast<const float4*>(base + (size_t)(j0 + k) * 512));
#pragma unroll
        for (int k = 0; k < 8; k++) {
            a1.x += v[k].x; a1.y += v[k].y; a1.z += v[k].z; a1.w += v[k].w;
        }
    }

    const int ihi = g >> 5;          // row half
    __shared__ float4 part[4][32][8];            // [quad][row-subgroup][lane], 16 KB
    __shared__ float  quads[4][32];              // [quad][m_local]
    part[ihi * 2 + 0][g & 31][lane] = a0;
    part[ihi * 2 + 1][g & 31][lane] = a1;
    __syncthreads();

    if (tid < 32) {
        // Reduce 32 row-partials per (quad, lane)
        const int quad = tid >> 3, ln = tid & 7;
        float4 ssum = {0.f,0.f,0.f,0.f};
#pragma unroll
        for (int k = 0; k < 32; k++) {
            float4 v = part[quad][k][ln];
            ssum.x += v.x; ssum.y += v.y; ssum.z += v.z; ssum.w += v.w;
        }
        quads[quad][ln * 4 + 0] = ssum.x;
        quads[quad][ln * 4 + 1] = ssum.y;
        quads[quad][ln * 4 + 2] = ssum.z;
        quads[quad][ln * 4 + 3] = ssum.w;
        __syncwarp();

        // Each of the 32 threads simulates one sample
        const int mm = mc * 32 + tid;            // global m in [0,512)
        float x[4];
#pragma unroll
        for (int q = 0; q < 4; q++)
            x[q] = tanhf(quads[q][tid] * (1.0f / 1024.0f));

        // widx = (b*512 + mm) // 64 = b*8 + (mm >> 6); 24 floats per widx
        const float* wp = w + ((size_t)(b * 8 + (mm >> 6))) * 24;
        out[b * 512 + mm] = simulate_sample(x, wp);
    }
}

extern "C" void kernel_launch(void* const* d_in, const int* in_sizes, int n_in,
                              void* d_out, int out_size)
{
    const float* in = (const float*)d_in[0];
    const float* w  = (const float*)d_in[1];
    // Defensive: identify tensors by size (inputs = 134217728 elems, weights = 12288)
    if (n_in >= 2 && in_sizes[0] < in_sizes[1]) {
        in = (const float*)d_in[1];
        w  = (const float*)d_in[0];
    }
    dim3 grid(16, 64);
    qpl_kernel<<<grid, 512>>>(in, w, (float*)d_out);
}